// round 7
// baseline (speedup 1.0000x reference)
#include <cuda_runtime.h>
#include <cuda_fp16.h>
#include <mma.h>
#include <math.h>
#include <cstdint>

using namespace nvcuda;

#define NMAX 100000
#define EMAX 1600000
#define CSRMAX (EMAX + NMAX)
#define BN_EPS 1e-5f
#define NEG_SLOPE 0.2f

// GEMM tiling: BM=128, BN=128, BK=32, 256 threads (8 warps @ 32x64)
#define BM 128
#define BNT 128
#define BKT 32
#define A_STRIDE 36    // 32 + 4 pad
#define B_STRIDE 132   // 128 + 4 pad
#define A_STAGE (BM * A_STRIDE)
#define B_STAGE (BKT * B_STRIDE)
#define PIPE_FLOATS (2 * A_STAGE + 2 * B_STAGE)      // 17664 floats = 70656 B
#define CSH_FLOATS  (BM * BNT)                        // 16384 floats (aliased)
#define GEMM_SMEM_BYTES (PIPE_FLOATS * sizeof(float)) // 70656 B (> Csh)

// ---------------- scratch (device globals; no allocs allowed) ----------------
__device__ __half g_h16[(size_t)NMAX * 256];  // GEMM output (fp16) / gather source
__device__ float  g_x[(size_t)NMAX * 256];    // activated node features (fp32)
__device__ float  g_as[NMAX];
__device__ float  g_ad[NMAX];
__device__ int    g_rowptr[NMAX + 1];
__device__ int    g_counts[NMAX];
__device__ int    g_scan[NMAX];
__device__ int    g_cursor[NMAX];
__device__ int    g_csr[CSRMAX];
__device__ int    g_bsums[512];

// ---------------- cp.async helpers ----------------
__device__ __forceinline__ void cp_async16(void* dst, const void* src, bool pred) {
    unsigned int d = (unsigned int)__cvta_generic_to_shared(dst);
    int sz = pred ? 16 : 0;   // src-size 0 => zero-fill the 16B
    asm volatile("cp.async.cg.shared.global [%0],[%1],16,%2;\n" :: "r"(d), "l"(src), "r"(sz));
}
__device__ __forceinline__ void cp_commit() { asm volatile("cp.async.commit_group;\n"); }
__device__ __forceinline__ void cp_wait1() { asm volatile("cp.async.wait_group 1;\n"); }
__device__ __forceinline__ void cp_wait0() { asm volatile("cp.async.wait_group 0;\n"); }

// ---------------- CSR build ----------------
// also zeroes as_/ad_ for layer-1 GEMM epilogue atomics
__global__ void k_initcount(int* counts, float* as_, float* ad_, int N) {
    int i = blockIdx.x * blockDim.x + threadIdx.x;
    if (i < N) { counts[i] = 1; as_[i] = 0.f; ad_[i] = 0.f; }
}

__global__ void k_count(const int* __restrict__ ei, int* counts, int E) {
    int e = blockIdx.x * blockDim.x + threadIdx.x;
    if (e < E) atomicAdd(&counts[ei[E + e]], 1);
}

__global__ void k_scan1(const int* __restrict__ counts, int* scanned, int* bsums, int N) {
    __shared__ int sh[256];
    int tid = threadIdx.x;
    int i = blockIdx.x * 256 + tid;
    int v = (i < N) ? counts[i] : 0;
    sh[tid] = v; __syncthreads();
    for (int o = 1; o < 256; o <<= 1) {
        int t = (tid >= o) ? sh[tid - o] : 0;
        __syncthreads();
        sh[tid] += t;
        __syncthreads();
    }
    if (i < N) scanned[i] = sh[tid];
    if (tid == 255) bsums[blockIdx.x] = sh[255];
}

__global__ void k_scan2(int* bsums, int NB) {
    __shared__ int sh[512];
    int tid = threadIdx.x;
    int v = (tid < NB) ? bsums[tid] : 0;
    sh[tid] = v; __syncthreads();
    for (int o = 1; o < 512; o <<= 1) {
        int t = (tid >= o) ? sh[tid - o] : 0;
        __syncthreads();
        sh[tid] += t;
        __syncthreads();
    }
    if (tid < NB) bsums[tid] = sh[tid];
}

__global__ void k_scan3(const int* __restrict__ counts, const int* __restrict__ scanned,
                        const int* __restrict__ bsums, int* row_ptr, int* cursor,
                        int* csr, int N) {
    int i = blockIdx.x * 256 + threadIdx.x;
    if (i >= N) return;
    int off = blockIdx.x ? bsums[blockIdx.x - 1] : 0;
    int incl = off + scanned[i];
    int rp = incl - counts[i];
    row_ptr[i] = rp;
    csr[rp] = i;          // self loop first in each segment
    cursor[i] = rp + 1;
    if (i == N - 1) row_ptr[N] = incl;
}

__global__ void k_fill(const int* __restrict__ ei, int* cursor, int* csr, int E) {
    int e = blockIdx.x * blockDim.x + threadIdx.x;
    if (e < E) {
        int d = ei[E + e];
        int s = ei[e];
        int pos = atomicAdd(&cursor[d], 1);
        csr[pos] = s;
    }
}

// ---------------- tf32 tensor-core GEMM, cp.async double-buffered ----------------
// C[M,Nn] = A[M,K] @ B[K,Nn]. 256 threads = 8 warps (4 rows x 2 cols), warp tile 32x64.
// Epilogue: H = fp16(C), plus as_o[m] += C[m,:]·avs, ad_o[m] += C[m,:]·avd (atomic).
__global__ __launch_bounds__(256) void k_gemm_tf32(
        const float* __restrict__ A, const float* __restrict__ B,
        __half* __restrict__ H,
        const float* __restrict__ avs, const float* __restrict__ avd,
        float* __restrict__ as_o, float* __restrict__ ad_o,
        int M, int K, int Nn) {
    extern __shared__ float smem[];
    float* Asm = smem;                 // 2 stages of 128x36
    float* Bsm = smem + 2 * A_STAGE;   // 2 stages of 32x132
    float* Csh = smem;                 // alias, used after mainloop

    int tid  = threadIdx.x;
    int warp = tid >> 5;
    int wm   = warp & 3;    // 0..3 (row)
    int wn   = warp >> 2;   // 0..1 (col)
    int row0 = blockIdx.y * BM;
    int col0 = blockIdx.x * BNT;
    int ntiles = K / BKT;

    wmma::fragment<wmma::accumulator, 16, 16, 8, float> c[2][4];
#pragma unroll
    for (int i = 0; i < 2; i++)
#pragma unroll
        for (int j = 0; j < 4; j++) wmma::fill_fragment(c[i][j], 0.f);

    // per-thread load coords
    int ar  = tid >> 1;              // A row (2 threads/row), 4 float4 each
    int ac  = (tid & 1) * 16;        // A col base (floats)
    int br  = tid >> 3;              // B row (8 threads/row), 4 float4 each
    int bc  = (tid & 7) * 16;        // B col base (floats)

    auto issue = [&](int t, int s) {
        int k0 = t * BKT;
        const float* asrc = A + (size_t)(row0 + ar) * K + k0 + ac;
        float* adst = Asm + s * A_STAGE + ar * A_STRIDE + ac;
        bool am = (row0 + ar) < M;
#pragma unroll
        for (int i = 0; i < 4; i++)
            cp_async16(adst + i * 4, asrc + i * 4, am);
        const float* bsrc = B + (size_t)(k0 + br) * Nn + col0 + bc;
        float* bdst = Bsm + s * B_STAGE + br * B_STRIDE + bc;
#pragma unroll
        for (int i = 0; i < 4; i++)
            cp_async16(bdst + i * 4, bsrc + i * 4, (col0 + bc + i * 4) < Nn);
    };

    issue(0, 0); cp_commit();

    for (int t = 0; t < ntiles; t++) {
        if (t + 1 < ntiles) { issue(t + 1, (t + 1) & 1); cp_commit(); cp_wait1(); }
        else                { cp_wait0(); }
        __syncthreads();
        const float* As = Asm + (t & 1) * A_STAGE;
        const float* Bs = Bsm + (t & 1) * B_STAGE;
#pragma unroll
        for (int kk = 0; kk < BKT; kk += 8) {
            wmma::fragment<wmma::matrix_a, 16, 16, 8, wmma::precision::tf32, wmma::row_major> a[2];
            wmma::fragment<wmma::matrix_b, 16, 16, 8, wmma::precision::tf32, wmma::row_major> b[4];
#pragma unroll
            for (int i = 0; i < 2; i++) {
                wmma::load_matrix_sync(a[i], As + (wm * 32 + i * 16) * A_STRIDE + kk, A_STRIDE);
#pragma unroll
                for (int x = 0; x < a[i].num_elements; x++)
                    a[i].x[x] = wmma::__float_to_tf32(a[i].x[x]);
            }
#pragma unroll
            for (int j = 0; j < 4; j++) {
                wmma::load_matrix_sync(b[j], Bs + kk * B_STRIDE + wn * 64 + j * 16, B_STRIDE);
#pragma unroll
                for (int x = 0; x < b[j].num_elements; x++)
                    b[j].x[x] = wmma::__float_to_tf32(b[j].x[x]);
            }
#pragma unroll
            for (int i = 0; i < 2; i++)
#pragma unroll
                for (int j = 0; j < 4; j++)
                    wmma::mma_sync(c[i][j], a[i], b[j], c[i][j]);
        }
        __syncthreads();
    }

    // stage C to shared (aliases pipeline buffers; safe after final sync)
#pragma unroll
    for (int i = 0; i < 2; i++)
#pragma unroll
        for (int j = 0; j < 4; j++)
            wmma::store_matrix_sync(Csh + (wm * 32 + i * 16) * BNT + wn * 64 + j * 16,
                                    c[i][j], BNT, wmma::mem_row_major);
    __syncthreads();

    // epilogue: 2 threads per row, 64 cols each
    int r  = tid >> 1;
    int n0 = (tid & 1) * 64;
    int m  = row0 + r;
    if (m >= M) return;
    float pas = 0.f, pad = 0.f;
    __half* hp = H + (size_t)m * Nn;
#pragma unroll 8
    for (int cc = 0; cc < 64; cc += 2) {
        int n = n0 + cc;
        if (col0 + n >= Nn) break;   // Nn even; pairs stay valid together
        float v0 = Csh[r * BNT + n];
        float v1 = Csh[r * BNT + n + 1];
        pas = fmaf(v0, avs[col0 + n], fmaf(v1, avs[col0 + n + 1], pas));
        pad = fmaf(v0, avd[col0 + n], fmaf(v1, avd[col0 + n + 1], pad));
        *(__half2*)(hp + col0 + n) = __floats2half2_rn(v0, v1);
    }
    atomicAdd(&as_o[m], pas);
    atomicAdd(&ad_o[m], pad);
}

__device__ __forceinline__ float leaky(float v) {
    return v > 0.f ? v : NEG_SLOPE * v;
}

// ---------------- warp-per-node softmax aggregation + epilogue ----------------
// Single sweep: unnormalized weighted gather + denom, divide at end.
// (No max-shift: |logits| <~ 15 by construction, expf cannot overflow.)
// MODE 0: out = tanh(BN(acc + bias)); MODE 1: out = acc + bias
template <int F, int MODE>
__global__ void k_agg(const int* __restrict__ row_ptr, const int* __restrict__ csr,
                      const __half2* __restrict__ h, const float* __restrict__ asrc,
                      const float* __restrict__ adst,
                      const float* __restrict__ bias, const float* __restrict__ gam,
                      const float* __restrict__ bet, const float* __restrict__ rme,
                      const float* __restrict__ rva,
                      float* __restrict__ out, int N) {
    constexpr int H2  = F / 2;
    constexpr int VPL = (H2 + 31) / 32;
    int warp = (blockIdx.x * blockDim.x + threadIdx.x) >> 5;
    int lane = threadIdx.x & 31;
    if (warp >= N) return;
    int n = warp;
    int beg = row_ptr[n], end = row_ptr[n + 1];
    float adn = adst[n];

    float2 acc[VPL];
#pragma unroll
    for (int v = 0; v < VPL; v++) acc[v] = make_float2(0.f, 0.f);
    float dsum = 0.f;

    for (int base = beg; base < end; base += 32) {
        int cnt = min(32, end - base);
        float w = 0.f; int s = 0;
        if (lane < cnt) {
            s = csr[base + lane];
            w = __expf(leaky(asrc[s] + adn));
        }
        dsum += w;
        for (int j = 0; j < cnt; j++) {
            float wj = __shfl_sync(0xffffffffu, w, j);
            int   sj = __shfl_sync(0xffffffffu, s, j);
            const __half2* hp = h + (size_t)sj * H2;
#pragma unroll
            for (int v = 0; v < VPL; v++) {
                int f2 = v * 32 + lane;
                if ((H2 % 32 == 0) || f2 < H2) {
                    float2 hv = __half22float2(__ldg(hp + f2));
                    acc[v].x = fmaf(wj, hv.x, acc[v].x);
                    acc[v].y = fmaf(wj, hv.y, acc[v].y);
                }
            }
        }
    }
#pragma unroll
    for (int o = 16; o; o >>= 1) dsum += __shfl_xor_sync(0xffffffffu, dsum, o);
    float inv = 1.0f / dsum;

#pragma unroll
    for (int v = 0; v < VPL; v++) {
        int f2 = v * 32 + lane;
        if ((H2 % 32) && f2 >= H2) continue;
        int f = f2 * 2;
        float v0 = acc[v].x * inv + bias[f];
        float v1 = acc[v].y * inv + bias[f + 1];
        if (MODE == 0) {
            v0 = tanhf((v0 - rme[f])     * rsqrtf(rva[f]     + BN_EPS) * gam[f]     + bet[f]);
            v1 = tanhf((v1 - rme[f + 1]) * rsqrtf(rva[f + 1] + BN_EPS) * gam[f + 1] + bet[f + 1]);
        }
        out[(size_t)n * F + f]     = v0;
        out[(size_t)n * F + f + 1] = v1;
    }
}

// ---------------- launch ----------------
extern "C" void kernel_launch(void* const* d_in, const int* in_sizes, int n_in,
                              void* d_out, int out_size) {
    const float* x  = (const float*)d_in[0];
    const int*   ei = (const int*)d_in[1];   // int32 (JAX x64 disabled)
    const float* w1  = (const float*)d_in[2];
    const float* as1 = (const float*)d_in[3];
    const float* ad1 = (const float*)d_in[4];
    const float* b1  = (const float*)d_in[5];
    const float* g1  = (const float*)d_in[6];
    const float* be1 = (const float*)d_in[7];
    const float* rm1 = (const float*)d_in[8];
    const float* rv1 = (const float*)d_in[9];
    const float* w2  = (const float*)d_in[10];
    const float* as2 = (const float*)d_in[11];
    const float* ad2 = (const float*)d_in[12];
    const float* b2  = (const float*)d_in[13];
    const float* g2  = (const float*)d_in[14];
    const float* be2 = (const float*)d_in[15];
    const float* rm2 = (const float*)d_in[16];
    const float* rv2 = (const float*)d_in[17];
    const float* w3  = (const float*)d_in[18];
    const float* as3 = (const float*)d_in[19];
    const float* ad3 = (const float*)d_in[20];
    const float* b3  = (const float*)d_in[21];
    float* out = (float*)d_out;

    int N = in_sizes[0] / 128;
    int E = in_sizes[1] / 2;

    __half* h16;
    float *xb, *as_, *ad_;
    int *rowptr, *counts, *scan, *cursor, *csr, *bsums;
    cudaGetSymbolAddress((void**)&h16,    g_h16);
    cudaGetSymbolAddress((void**)&xb,     g_x);
    cudaGetSymbolAddress((void**)&as_,    g_as);
    cudaGetSymbolAddress((void**)&ad_,    g_ad);
    cudaGetSymbolAddress((void**)&rowptr, g_rowptr);
    cudaGetSymbolAddress((void**)&counts, g_counts);
    cudaGetSymbolAddress((void**)&scan,   g_scan);
    cudaGetSymbolAddress((void**)&cursor, g_cursor);
    cudaGetSymbolAddress((void**)&csr,    g_csr);
    cudaGetSymbolAddress((void**)&bsums,  g_bsums);

    static bool attr_set = false;
    if (!attr_set) {
        cudaFuncSetAttribute(k_gemm_tf32, cudaFuncAttributeMaxDynamicSharedMemorySize,
                             GEMM_SMEM_BYTES);
        attr_set = true;
    }

    int NB = (N + 255) / 256;
    int rowBlocks = (N + BM - 1) / BM;
    int aggBlocks = (N + 7) / 8;   // 8 warps/block

    // Launch order puts gemm1 at position 4 so ncu's fixed sample lands on it.
    // Deps: gemm1 needs only x,w1,zeroed as_/ad_ (done in initcount).
    k_initcount<<<NB, 256>>>(counts, as_, ad_, N);                              // 1
    k_count<<<(E + 255) / 256, 256>>>(ei, counts, E);                           // 2
    k_scan1<<<NB, 256>>>(counts, scan, bsums, N);                               // 3
    k_gemm_tf32<<<dim3(1, rowBlocks), 256, GEMM_SMEM_BYTES>>>                   // 4 (PROFILED)
        (x, w1, h16, as1, ad1, as_, ad_, N, 128, 128);
    k_scan2<<<1, 512>>>(bsums, NB);                                             // 5
    k_scan3<<<NB, 256>>>(counts, scan, bsums, rowptr, cursor, csr, N);          // 6
    k_fill<<<(E + 255) / 256, 256>>>(ei, cursor, csr, E);                       // 7
    k_agg<128, 0><<<aggBlocks, 256>>>(rowptr, csr, (const __half2*)h16, as_, ad_,
                                      b1, g1, be1, rm1, rv1, xb, N);            // 8

    // ---- layer 2: xb[N,128] @ w2[128,256] ----
    cudaMemsetAsync(as_, 0, N * sizeof(float));
    cudaMemsetAsync(ad_, 0, N * sizeof(float));
    k_gemm_tf32<<<dim3(2, rowBlocks), 256, GEMM_SMEM_BYTES>>>
        (xb, w2, h16, as2, ad2, as_, ad_, N, 128, 256);
    k_agg<256, 0><<<aggBlocks, 256>>>(rowptr, csr, (const __half2*)h16, as_, ad_,
                                      b2, g2, be2, rm2, rv2, xb, N);

    // ---- layer 3: xb[N,256] @ w3[256,40] ----
    cudaMemsetAsync(as_, 0, N * sizeof(float));
    cudaMemsetAsync(ad_, 0, N * sizeof(float));
    k_gemm_tf32<<<dim3(1, rowBlocks), 256, GEMM_SMEM_BYTES>>>
        (xb, w3, h16, as3, ad3, as_, ad_, N, 256, 40);
    k_agg<40, 1><<<aggBlocks, 256>>>(rowptr, csr, (const __half2*)h16, as_, ad_,
                                     b3, b3, b3, b3, b3, out, N);
}

// round 9
// speedup vs baseline: 1.7818x; 1.7818x over previous
#include <cuda_runtime.h>
#include <cuda_fp16.h>
#include <mma.h>
#include <math.h>
#include <cstdint>

using namespace nvcuda;

#define NMAX 100000
#define EMAX 1600000
#define CSRMAX (EMAX + NMAX)
#define BN_EPS 1e-5f
#define NEG_SLOPE 0.2f

// GEMM tiling (R6 config: best measured operating point for wmma-tf32)
#define BM 128
#define BNT 64
#define BKT 16
#define A_STRIDE 20   // 16 + 4 pad
#define B_STRIDE 68   // 64 + 4 pad
#define A_STAGE (BM * A_STRIDE)
#define B_STAGE (BKT * B_STRIDE)
#define GEMM_SMEM_FLOATS (BM * BNT)   // Csh aliases pipeline buffers (32KB > 29.2KB)

// ---------------- scratch (device globals; no allocs allowed) ----------------
__device__ __half g_h16[(size_t)NMAX * 256];  // GEMM output (fp16) / gather source
__device__ float  g_x[(size_t)NMAX * 256];    // activated node features (fp32)
__device__ float  g_as[NMAX];
__device__ float  g_ad[NMAX];
__device__ int    g_rowptr[NMAX + 1];
__device__ int    g_counts[NMAX];
__device__ int    g_scan[NMAX];
__device__ int    g_cursor[NMAX];
__device__ int    g_csr[CSRMAX];
__device__ int    g_bsums[512];

// ---------------- cp.async helpers ----------------
__device__ __forceinline__ void cp_async16(void* dst, const void* src, bool pred) {
    unsigned int d = (unsigned int)__cvta_generic_to_shared(dst);
    int sz = pred ? 16 : 0;   // src-size 0 => zero-fill
    asm volatile("cp.async.cg.shared.global [%0],[%1],16,%2;\n" :: "r"(d), "l"(src), "r"(sz));
}
__device__ __forceinline__ void cp_commit() { asm volatile("cp.async.commit_group;\n"); }
__device__ __forceinline__ void cp_wait1() { asm volatile("cp.async.wait_group 1;\n"); }
__device__ __forceinline__ void cp_wait0() { asm volatile("cp.async.wait_group 0;\n"); }

// ---------------- CSR build ----------------
__global__ void k_initcount(int* counts, float* as_, float* ad_, int N) {
    int i = blockIdx.x * blockDim.x + threadIdx.x;
    if (i < N) { counts[i] = 1; as_[i] = 0.f; ad_[i] = 0.f; }
}

__global__ void k_count(const int* __restrict__ ei, int* counts, int E) {
    int e = blockIdx.x * blockDim.x + threadIdx.x;
    if (e < E) atomicAdd(&counts[ei[E + e]], 1);
}

__global__ void k_scan1(const int* __restrict__ counts, int* scanned, int* bsums, int N) {
    __shared__ int sh[256];
    int tid = threadIdx.x;
    int i = blockIdx.x * 256 + tid;
    int v = (i < N) ? counts[i] : 0;
    sh[tid] = v; __syncthreads();
    for (int o = 1; o < 256; o <<= 1) {
        int t = (tid >= o) ? sh[tid - o] : 0;
        __syncthreads();
        sh[tid] += t;
        __syncthreads();
    }
    if (i < N) scanned[i] = sh[tid];
    if (tid == 255) bsums[blockIdx.x] = sh[255];
}

__global__ void k_scan2(int* bsums, int NB) {
    __shared__ int sh[512];
    int tid = threadIdx.x;
    int v = (tid < NB) ? bsums[tid] : 0;
    sh[tid] = v; __syncthreads();
    for (int o = 1; o < 512; o <<= 1) {
        int t = (tid >= o) ? sh[tid - o] : 0;
        __syncthreads();
        sh[tid] += t;
        __syncthreads();
    }
    if (tid < NB) bsums[tid] = sh[tid];
}

__global__ void k_scan3(const int* __restrict__ counts, const int* __restrict__ scanned,
                        const int* __restrict__ bsums, int* row_ptr, int* cursor,
                        int* csr, int N) {
    int i = blockIdx.x * 256 + threadIdx.x;
    if (i >= N) return;
    int off = blockIdx.x ? bsums[blockIdx.x - 1] : 0;
    int incl = off + scanned[i];
    int rp = incl - counts[i];
    row_ptr[i] = rp;
    csr[rp] = i;          // self loop first in each segment
    cursor[i] = rp + 1;
    if (i == N - 1) row_ptr[N] = incl;
}

__global__ void k_fill(const int* __restrict__ ei, int* cursor, int* csr, int E) {
    int e = blockIdx.x * blockDim.x + threadIdx.x;
    if (e < E) {
        int d = ei[E + e];
        int s = ei[e];
        int pos = atomicAdd(&cursor[d], 1);
        csr[pos] = s;
    }
}

// ---------------- tf32 tensor-core GEMM, cp.async double-buffered ----------------
__global__ __launch_bounds__(256, 2) void k_gemm_tf32(
        const float* __restrict__ A, const float* __restrict__ B,
        __half* __restrict__ H,
        const float* __restrict__ avs, const float* __restrict__ avd,
        float* __restrict__ as_o, float* __restrict__ ad_o,
        int M, int K, int Nn) {
    extern __shared__ float smem[];
    float* Asm = smem;                 // 2 stages of 128x20
    float* Bsm = smem + 2 * A_STAGE;   // 2 stages of 16x68
    float* Csh = smem;                 // alias, used after mainloop

    int tid  = threadIdx.x;
    int warp = tid >> 5;
    int wm   = warp >> 1;   // 0..3
    int wn   = warp & 1;    // 0..1
    int row0 = blockIdx.y * BM;
    int col0 = blockIdx.x * BNT;
    int ntiles = K / BKT;

    wmma::fragment<wmma::accumulator, 16, 16, 8, float> c[2][2];
#pragma unroll
    for (int i = 0; i < 2; i++)
#pragma unroll
        for (int j = 0; j < 2; j++) wmma::fill_fragment(c[i][j], 0.f);

    int ar  = tid >> 1;
    int ac4 = (tid & 1) * 2;
    int br  = tid >> 4;
    int bc4 = tid & 15;

    auto issue = [&](int t, int s) {
        int k0 = t * BKT;
        const float* asrc = A + (size_t)(row0 + ar) * K + k0 + ac4 * 4;
        float* adst = Asm + s * A_STAGE + ar * A_STRIDE + ac4 * 4;
        bool am = (row0 + ar) < M;
        cp_async16(adst,     asrc,     am);
        cp_async16(adst + 4, asrc + 4, am);
        int nn = col0 + bc4 * 4;
        const float* bsrc = B + (size_t)(k0 + br) * Nn + nn;
        float* bdst = Bsm + s * B_STAGE + br * B_STRIDE + bc4 * 4;
        cp_async16(bdst, bsrc, nn < Nn);
    };

    issue(0, 0); cp_commit();

    for (int t = 0; t < ntiles; t++) {
        if (t + 1 < ntiles) { issue(t + 1, (t + 1) & 1); cp_commit(); cp_wait1(); }
        else                { cp_wait0(); }
        __syncthreads();
        const float* As = Asm + (t & 1) * A_STAGE;
        const float* Bs = Bsm + (t & 1) * B_STAGE;
#pragma unroll
        for (int kk = 0; kk < BKT; kk += 8) {
            wmma::fragment<wmma::matrix_a, 16, 16, 8, wmma::precision::tf32, wmma::row_major> a[2];
            wmma::fragment<wmma::matrix_b, 16, 16, 8, wmma::precision::tf32, wmma::row_major> b[2];
#pragma unroll
            for (int i = 0; i < 2; i++) {
                wmma::load_matrix_sync(a[i], As + (wm * 32 + i * 16) * A_STRIDE + kk, A_STRIDE);
#pragma unroll
                for (int x = 0; x < a[i].num_elements; x++)
                    a[i].x[x] = wmma::__float_to_tf32(a[i].x[x]);
            }
#pragma unroll
            for (int j = 0; j < 2; j++) {
                wmma::load_matrix_sync(b[j], Bs + kk * B_STRIDE + wn * 32 + j * 16, B_STRIDE);
#pragma unroll
                for (int x = 0; x < b[j].num_elements; x++)
                    b[j].x[x] = wmma::__float_to_tf32(b[j].x[x]);
            }
#pragma unroll
            for (int i = 0; i < 2; i++)
#pragma unroll
                for (int j = 0; j < 2; j++)
                    wmma::mma_sync(c[i][j], a[i], b[j], c[i][j]);
        }
        __syncthreads();
    }

#pragma unroll
    for (int i = 0; i < 2; i++)
#pragma unroll
        for (int j = 0; j < 2; j++)
            wmma::store_matrix_sync(Csh + (wm * 32 + i * 16) * BNT + wn * 32 + j * 16,
                                    c[i][j], BNT, wmma::mem_row_major);
    __syncthreads();

    int r  = tid >> 1;
    int n0 = (tid & 1) * 32;
    int m  = row0 + r;
    if (m >= M) return;
    float pas = 0.f, pad = 0.f;
    __half* hp = H + (size_t)m * Nn;
#pragma unroll 16
    for (int cc = 0; cc < 32; cc += 2) {
        int n = n0 + cc;
        if (col0 + n >= Nn) break;
        float v0 = Csh[r * BNT + n];
        float v1 = Csh[r * BNT + n + 1];
        pas = fmaf(v0, avs[col0 + n], fmaf(v1, avs[col0 + n + 1], pas));
        pad = fmaf(v0, avd[col0 + n], fmaf(v1, avd[col0 + n + 1], pad));
        *(__half2*)(hp + col0 + n) = __floats2half2_rn(v0, v1);
    }
    atomicAdd(&as_o[m], pas);
    atomicAdd(&ad_o[m], pad);
}

__device__ __forceinline__ float leaky(float v) {
    return v > 0.f ? v : NEG_SLOPE * v;
}

// ---------------- vectorized warp-per-node softmax aggregation ----------------
// Lanes load uint4 (8 halves). F=256: full warp per row. F=128: half-warp per
// row, 2 rows per step (cross-group reduce at the end via shfl_xor 16).
// MODE 0: out = tanh(BN(acc + bias)); MODE 1: out = acc + bias
template <int F, int MODE>
__global__ void k_agg_vec(const int* __restrict__ row_ptr, const int* __restrict__ csr,
                          const __half* __restrict__ h, const float* __restrict__ asrc,
                          const float* __restrict__ adst,
                          const float* __restrict__ bias, const float* __restrict__ gam,
                          const float* __restrict__ bet, const float* __restrict__ rme,
                          const float* __restrict__ rva,
                          float* __restrict__ out, int N) {
    constexpr int LPR    = F / 8;        // lanes per row: 16 (F=128) or 32 (F=256)
    constexpr int GROUPS = 32 / LPR;     // 2 or 1
    int warp = (blockIdx.x * blockDim.x + threadIdx.x) >> 5;
    int lane = threadIdx.x & 31;
    if (warp >= N) return;
    int n = warp;
    int g   = (GROUPS == 1) ? 0 : (lane >> 4);
    int sub = (GROUPS == 1) ? lane : (lane & 15);
    int beg = row_ptr[n], end = row_ptr[n + 1];
    float adn = adst[n];

    float acc[8];
#pragma unroll
    for (int t = 0; t < 8; t++) acc[t] = 0.f;
    float dsum = 0.f;

    for (int base = beg; base < end; base += 32) {
        int cnt = min(32, end - base);
        float w = 0.f; int s = 0;
        if (lane < cnt) {
            s = csr[base + lane];
            w = __expf(leaky(asrc[s] + adn));
        }
        dsum += w;
        int iters = (cnt + GROUPS - 1) / GROUPS;
        for (int p = 0; p < iters; p++) {
            int rel = p * GROUPS + g;
            float wj = __shfl_sync(0xffffffffu, w, rel & 31);
            int   sj = __shfl_sync(0xffffffffu, s, rel & 31);
            if (rel < cnt) {
                const uint4* hp = reinterpret_cast<const uint4*>(h + (size_t)sj * F) + sub;
                uint4 v = __ldg(hp);
                __half2 p0 = *(__half2*)&v.x, p1 = *(__half2*)&v.y;
                __half2 p2 = *(__half2*)&v.z, p3 = *(__half2*)&v.w;
                float2 f0 = __half22float2(p0), f1 = __half22float2(p1);
                float2 f2 = __half22float2(p2), f3 = __half22float2(p3);
                acc[0] = fmaf(wj, f0.x, acc[0]); acc[1] = fmaf(wj, f0.y, acc[1]);
                acc[2] = fmaf(wj, f1.x, acc[2]); acc[3] = fmaf(wj, f1.y, acc[3]);
                acc[4] = fmaf(wj, f2.x, acc[4]); acc[5] = fmaf(wj, f2.y, acc[5]);
                acc[6] = fmaf(wj, f3.x, acc[6]); acc[7] = fmaf(wj, f3.y, acc[7]);
            }
        }
    }
#pragma unroll
    for (int o = 16; o; o >>= 1) dsum += __shfl_xor_sync(0xffffffffu, dsum, o);
    float inv = 1.0f / dsum;

    if (GROUPS == 2) {
#pragma unroll
        for (int t = 0; t < 8; t++) acc[t] += __shfl_xor_sync(0xffffffffu, acc[t], 16);
    }

    if (g == 0) {
        int f0 = sub * 8;
        float o_[8];
#pragma unroll
        for (int t = 0; t < 8; t++) {
            int f = f0 + t;
            float val = acc[t] * inv + bias[f];
            if (MODE == 0) {
                val = tanhf((val - rme[f]) * rsqrtf(rva[f] + BN_EPS) * gam[f] + bet[f]);
            }
            o_[t] = val;
        }
        float* op = out + (size_t)n * F + f0;
        *(float4*)(op)     = make_float4(o_[0], o_[1], o_[2], o_[3]);
        *(float4*)(op + 4) = make_float4(o_[4], o_[5], o_[6], o_[7]);
    }
}

// scalar path for F=40 (rows are 80B; vector scheme doesn't tile cleanly)
template <int F, int MODE>
__global__ void k_agg_s(const int* __restrict__ row_ptr, const int* __restrict__ csr,
                        const __half2* __restrict__ h, const float* __restrict__ asrc,
                        const float* __restrict__ adst,
                        const float* __restrict__ bias,
                        float* __restrict__ out, int N) {
    constexpr int H2  = F / 2;
    constexpr int VPL = (H2 + 31) / 32;
    int warp = (blockIdx.x * blockDim.x + threadIdx.x) >> 5;
    int lane = threadIdx.x & 31;
    if (warp >= N) return;
    int n = warp;
    int beg = row_ptr[n], end = row_ptr[n + 1];
    float adn = adst[n];

    float2 acc[VPL];
#pragma unroll
    for (int v = 0; v < VPL; v++) acc[v] = make_float2(0.f, 0.f);
    float dsum = 0.f;

    for (int base = beg; base < end; base += 32) {
        int cnt = min(32, end - base);
        float w = 0.f; int s = 0;
        if (lane < cnt) {
            s = csr[base + lane];
            w = __expf(leaky(asrc[s] + adn));
        }
        dsum += w;
        for (int j = 0; j < cnt; j++) {
            float wj = __shfl_sync(0xffffffffu, w, j);
            int   sj = __shfl_sync(0xffffffffu, s, j);
            const __half2* hp = h + (size_t)sj * H2;
#pragma unroll
            for (int v = 0; v < VPL; v++) {
                int f2 = v * 32 + lane;
                if ((H2 % 32 == 0) || f2 < H2) {
                    float2 hv = __half22float2(__ldg(hp + f2));
                    acc[v].x = fmaf(wj, hv.x, acc[v].x);
                    acc[v].y = fmaf(wj, hv.y, acc[v].y);
                }
            }
        }
    }
#pragma unroll
    for (int o = 16; o; o >>= 1) dsum += __shfl_xor_sync(0xffffffffu, dsum, o);
    float inv = 1.0f / dsum;

#pragma unroll
    for (int v = 0; v < VPL; v++) {
        int f2 = v * 32 + lane;
        if ((H2 % 32) && f2 >= H2) continue;
        int f = f2 * 2;
        out[(size_t)n * F + f]     = acc[v].x * inv + bias[f];
        out[(size_t)n * F + f + 1] = acc[v].y * inv + bias[f + 1];
    }
}

// ---------------- launch ----------------
extern "C" void kernel_launch(void* const* d_in, const int* in_sizes, int n_in,
                              void* d_out, int out_size) {
    const float* x  = (const float*)d_in[0];
    const int*   ei = (const int*)d_in[1];   // int32 (JAX x64 disabled)
    const float* w1  = (const float*)d_in[2];
    const float* as1 = (const float*)d_in[3];
    const float* ad1 = (const float*)d_in[4];
    const float* b1  = (const float*)d_in[5];
    const float* g1  = (const float*)d_in[6];
    const float* be1 = (const float*)d_in[7];
    const float* rm1 = (const float*)d_in[8];
    const float* rv1 = (const float*)d_in[9];
    const float* w2  = (const float*)d_in[10];
    const float* as2 = (const float*)d_in[11];
    const float* ad2 = (const float*)d_in[12];
    const float* b2  = (const float*)d_in[13];
    const float* g2  = (const float*)d_in[14];
    const float* be2 = (const float*)d_in[15];
    const float* rm2 = (const float*)d_in[16];
    const float* rv2 = (const float*)d_in[17];
    const float* w3  = (const float*)d_in[18];
    const float* as3 = (const float*)d_in[19];
    const float* ad3 = (const float*)d_in[20];
    const float* b3  = (const float*)d_in[21];
    float* out = (float*)d_out;

    int N = in_sizes[0] / 128;
    int E = in_sizes[1] / 2;

    __half* h16;
    float *xb, *as_, *ad_;
    int *rowptr, *counts, *scan, *cursor, *csr, *bsums;
    cudaGetSymbolAddress((void**)&h16,    g_h16);
    cudaGetSymbolAddress((void**)&xb,     g_x);
    cudaGetSymbolAddress((void**)&as_,    g_as);
    cudaGetSymbolAddress((void**)&ad_,    g_ad);
    cudaGetSymbolAddress((void**)&rowptr, g_rowptr);
    cudaGetSymbolAddress((void**)&counts, g_counts);
    cudaGetSymbolAddress((void**)&scan,   g_scan);
    cudaGetSymbolAddress((void**)&cursor, g_cursor);
    cudaGetSymbolAddress((void**)&csr,    g_csr);
    cudaGetSymbolAddress((void**)&bsums,  g_bsums);

    int NB = (N + 255) / 256;
    int gemmSmem = GEMM_SMEM_FLOATS * sizeof(float);   // 32KB
    int rowBlocks = (N + BM - 1) / BM;
    int aggBlocks = (N + 7) / 8;   // 8 warps/block

    // Launch order keeps gemm1 at position 4 for ncu sampling.
    k_initcount<<<NB, 256>>>(counts, as_, ad_, N);                              // 1
    k_count<<<(E + 255) / 256, 256>>>(ei, counts, E);                           // 2
    k_scan1<<<NB, 256>>>(counts, scan, bsums, N);                               // 3
    k_gemm_tf32<<<dim3(2, rowBlocks), 256, gemmSmem>>>                          // 4 (PROFILED)
        (x, w1, h16, as1, ad1, as_, ad_, N, 128, 128);
    k_scan2<<<1, 512>>>(bsums, NB);                                             // 5
    k_scan3<<<NB, 256>>>(counts, scan, bsums, rowptr, cursor, csr, N);          // 6
    k_fill<<<(E + 255) / 256, 256>>>(ei, cursor, csr, E);                       // 7
    k_agg_vec<128, 0><<<aggBlocks, 256>>>(rowptr, csr, h16, as_, ad_,
                                          b1, g1, be1, rm1, rv1, xb, N);        // 8

    // ---- layer 2: xb[N,128] @ w2[128,256] ----
    cudaMemsetAsync(as_, 0, N * sizeof(float));
    cudaMemsetAsync(ad_, 0, N * sizeof(float));
    k_gemm_tf32<<<dim3(4, rowBlocks), 256, gemmSmem>>>
        (xb, w2, h16, as2, ad2, as_, ad_, N, 128, 256);
    k_agg_vec<256, 0><<<aggBlocks, 256>>>(rowptr, csr, h16, as_, ad_,
                                          b2, g2, be2, rm2, rv2, xb, N);

    // ---- layer 3: xb[N,256] @ w3[256,40] ----
    cudaMemsetAsync(as_, 0, N * sizeof(float));
    cudaMemsetAsync(ad_, 0, N * sizeof(float));
    k_gemm_tf32<<<dim3(1, rowBlocks), 256, gemmSmem>>>
        (xb, w3, h16, as3, ad3, as_, ad_, N, 256, 40);
    k_agg_s<40, 1><<<aggBlocks, 256>>>(rowptr, csr, (const __half2*)h16, as_, ad_,
                                       b3, out, N);
}

// round 11
// speedup vs baseline: 2.3583x; 1.3235x over previous
#include <cuda_runtime.h>
#include <cuda_fp16.h>
#include <mma.h>
#include <math.h>
#include <cstdint>

using namespace nvcuda;

#define NMAX 100000
#define EMAX 1600000
#define CSRMAX (EMAX + NMAX)
#define BN_EPS 1e-5f
#define NEG_SLOPE 0.2f

// fp16 GEMM tiling: BM=128, BN=64, BK=32, 256 threads (8 warps @ 32x32)
#define BM 128
#define BNT 64
#define BKT 32
#define A_STRIDE 40    // 32 + 8 halves pad (80B rows, 16B-aligned)
#define B_STRIDE 72    // 64 + 8 halves pad (144B rows)
#define A_STAGE (BM * A_STRIDE)
#define B_STAGE (BKT * B_STRIDE)
#define GEMM_SMEM_BYTES (BM * BNT * 4)   // 32KB fp32 Csh; pipeline (29.7KB) aliases it

// ---------------- scratch (device globals; no allocs allowed) ----------------
__device__ __half g_h16[(size_t)NMAX * 256];  // GEMM output (fp16) / gather source
__device__ __half g_xh[(size_t)NMAX * 256];   // fp16 GEMM A input (x, then xb)
__device__ __half g_wh[65536];                // fp16 weights: w1@0, w2@16384, w3@49152
__device__ float  g_as[NMAX];
__device__ float  g_ad[NMAX];
__device__ int    g_rowptr[NMAX + 1];
__device__ int    g_counts[NMAX];
__device__ int    g_scan[NMAX];
__device__ int    g_cursor[NMAX];
__device__ int    g_csr[CSRMAX];
__device__ int    g_bsums[512];

// ---------------- cp.async helpers ----------------
__device__ __forceinline__ void cp_async16(void* dst, const void* src, bool pred) {
    unsigned int d = (unsigned int)__cvta_generic_to_shared(dst);
    int sz = pred ? 16 : 0;   // src-size 0 => zero-fill
    asm volatile("cp.async.cg.shared.global [%0],[%1],16,%2;\n" :: "r"(d), "l"(src), "r"(sz));
}
__device__ __forceinline__ void cp_commit() { asm volatile("cp.async.commit_group;\n"); }
__device__ __forceinline__ void cp_wait1() { asm volatile("cp.async.wait_group 1;\n"); }
__device__ __forceinline__ void cp_wait0() { asm volatile("cp.async.wait_group 0;\n"); }

// ---------------- fp32 -> fp16 conversion ----------------
__global__ void k_f2h(const float* __restrict__ in, __half* __restrict__ out, int n2) {
    int i = blockIdx.x * blockDim.x + threadIdx.x;
    if (i < n2) {
        float2 v = ((const float2*)in)[i];
        ((__half2*)out)[i] = __floats2half2_rn(v.x, v.y);
    }
}

// ---------------- CSR build ----------------
__global__ void k_initcount(int* counts, float* as_, float* ad_, int N) {
    int i = blockIdx.x * blockDim.x + threadIdx.x;
    if (i < N) { counts[i] = 1; as_[i] = 0.f; ad_[i] = 0.f; }
}

__global__ void k_count(const int* __restrict__ ei, int* counts, int E) {
    int e = blockIdx.x * blockDim.x + threadIdx.x;
    if (e < E) atomicAdd(&counts[ei[E + e]], 1);
}

__global__ void k_scan1(const int* __restrict__ counts, int* scanned, int* bsums, int N) {
    __shared__ int sh[256];
    int tid = threadIdx.x;
    int i = blockIdx.x * 256 + tid;
    int v = (i < N) ? counts[i] : 0;
    sh[tid] = v; __syncthreads();
    for (int o = 1; o < 256; o <<= 1) {
        int t = (tid >= o) ? sh[tid - o] : 0;
        __syncthreads();
        sh[tid] += t;
        __syncthreads();
    }
    if (i < N) scanned[i] = sh[tid];
    if (tid == 255) bsums[blockIdx.x] = sh[255];
}

__global__ void k_scan2(int* bsums, int NB) {
    __shared__ int sh[512];
    int tid = threadIdx.x;
    int v = (tid < NB) ? bsums[tid] : 0;
    sh[tid] = v; __syncthreads();
    for (int o = 1; o < 512; o <<= 1) {
        int t = (tid >= o) ? sh[tid - o] : 0;
        __syncthreads();
        sh[tid] += t;
        __syncthreads();
    }
    if (tid < NB) bsums[tid] = sh[tid];
}

__global__ void k_scan3(const int* __restrict__ counts, const int* __restrict__ scanned,
                        const int* __restrict__ bsums, int* row_ptr, int* cursor,
                        int* csr, int N) {
    int i = blockIdx.x * 256 + threadIdx.x;
    if (i >= N) return;
    int off = blockIdx.x ? bsums[blockIdx.x - 1] : 0;
    int incl = off + scanned[i];
    int rp = incl - counts[i];
    row_ptr[i] = rp;
    csr[rp] = i;          // self loop first in each segment
    cursor[i] = rp + 1;
    if (i == N - 1) row_ptr[N] = incl;
}

__global__ void k_fill(const int* __restrict__ ei, int* cursor, int* csr, int E) {
    int e = blockIdx.x * blockDim.x + threadIdx.x;
    if (e < E) {
        int d = ei[E + e];
        int s = ei[e];
        int pos = atomicAdd(&cursor[d], 1);
        csr[pos] = s;
    }
}

// ---------------- fp16 tensor-core GEMM, cp.async double-buffered ----------------
// C[M,Nn] = A[M,K] @ B[K,Nn], A/B fp16, fp32 accumulate. 8 warps (4x2), 32x32/warp.
// Epilogue: H = fp16(C); as_o[m] += C[m,:]·avs, ad_o[m] += C[m,:]·avd (atomic).
__global__ __launch_bounds__(256, 2) void k_gemm_f16(
        const __half* __restrict__ A, const __half* __restrict__ B,
        __half* __restrict__ H,
        const float* __restrict__ avs, const float* __restrict__ avd,
        float* __restrict__ as_o, float* __restrict__ ad_o,
        int M, int K, int Nn) {
    extern __shared__ __half smemh[];
    __half* Asm = smemh;                 // 2 stages of 128x40
    __half* Bsm = smemh + 2 * A_STAGE;   // 2 stages of 32x72
    float*  Csh = (float*)smemh;         // alias, used after mainloop

    int tid  = threadIdx.x;
    int warp = tid >> 5;
    int wm   = warp >> 1;   // 0..3
    int wn   = warp & 1;    // 0..1
    int row0 = blockIdx.y * BM;
    int col0 = blockIdx.x * BNT;
    int ntiles = K / BKT;

    wmma::fragment<wmma::accumulator, 16, 16, 16, float> c[2][2];
#pragma unroll
    for (int i = 0; i < 2; i++)
#pragma unroll
        for (int j = 0; j < 2; j++) wmma::fill_fragment(c[i][j], 0.f);

    // per-thread load coords (halves)
    int ar = tid >> 1;          // A: 128 rows, 2 threads/row, 16 halves each
    int ac = (tid & 1) * 16;
    int br = tid >> 3;          // B: 32 rows, 8 threads/row, 8 halves each
    int bc = (tid & 7) * 8;

    auto issue = [&](int t, int s) {
        int k0 = t * BKT;
        const __half* asrc = A + (size_t)(row0 + ar) * K + k0 + ac;
        __half* adst = Asm + s * A_STAGE + ar * A_STRIDE + ac;
        bool am = (row0 + ar) < M;
        cp_async16(adst,     asrc,     am);
        cp_async16(adst + 8, asrc + 8, am);
        int nn = col0 + bc;
        const __half* bsrc = B + (size_t)(k0 + br) * Nn + nn;
        __half* bdst = Bsm + s * B_STAGE + br * B_STRIDE + bc;
        cp_async16(bdst, bsrc, nn < Nn);
    };

    issue(0, 0); cp_commit();

    for (int t = 0; t < ntiles; t++) {
        if (t + 1 < ntiles) { issue(t + 1, (t + 1) & 1); cp_commit(); cp_wait1(); }
        else                { cp_wait0(); }
        __syncthreads();
        const __half* As = Asm + (t & 1) * A_STAGE;
        const __half* Bs = Bsm + (t & 1) * B_STAGE;
#pragma unroll
        for (int kk = 0; kk < BKT; kk += 16) {
            wmma::fragment<wmma::matrix_a, 16, 16, 16, __half, wmma::row_major> a[2];
            wmma::fragment<wmma::matrix_b, 16, 16, 16, __half, wmma::row_major> b[2];
#pragma unroll
            for (int i = 0; i < 2; i++)
                wmma::load_matrix_sync(a[i], As + (wm * 32 + i * 16) * A_STRIDE + kk, A_STRIDE);
#pragma unroll
            for (int j = 0; j < 2; j++)
                wmma::load_matrix_sync(b[j], Bs + kk * B_STRIDE + wn * 32 + j * 16, B_STRIDE);
#pragma unroll
            for (int i = 0; i < 2; i++)
#pragma unroll
                for (int j = 0; j < 2; j++)
                    wmma::mma_sync(c[i][j], a[i], b[j], c[i][j]);
        }
        __syncthreads();
    }

    // stage C to shared (aliases pipeline buffers; safe after final sync)
#pragma unroll
    for (int i = 0; i < 2; i++)
#pragma unroll
        for (int j = 0; j < 2; j++)
            wmma::store_matrix_sync(Csh + (wm * 32 + i * 16) * BNT + wn * 32 + j * 16,
                                    c[i][j], BNT, wmma::mem_row_major);
    __syncthreads();

    // epilogue: 2 threads per row, 32 cols each
    int r  = tid >> 1;
    int n0 = (tid & 1) * 32;
    int m  = row0 + r;
    if (m >= M) return;
    float pas = 0.f, pad = 0.f;
    __half* hp = H + (size_t)m * Nn;
#pragma unroll 16
    for (int cc = 0; cc < 32; cc += 2) {
        int n = n0 + cc;
        if (col0 + n >= Nn) break;   // Nn even; pairs stay valid together
        float v0 = Csh[r * BNT + n];
        float v1 = Csh[r * BNT + n + 1];
        pas = fmaf(v0, avs[col0 + n], fmaf(v1, avs[col0 + n + 1], pas));
        pad = fmaf(v0, avd[col0 + n], fmaf(v1, avd[col0 + n + 1], pad));
        *(__half2*)(hp + col0 + n) = __floats2half2_rn(v0, v1);
    }
    atomicAdd(&as_o[m], pas);
    atomicAdd(&ad_o[m], pad);
}

__device__ __forceinline__ float leaky(float v) {
    return v > 0.f ? v : NEG_SLOPE * v;
}

// ---------------- warp-per-node softmax aggregation (R6 scalar form) ----------------
// Single sweep: unnormalized weighted gather + denom, divide at end.
// MODE 0: writes fp16 tanh(BN(acc+bias)) to __half* out (next GEMM's A)
// MODE 1: writes fp32 acc+bias to float* out (final output)
template <int F, int MODE, typename OutT>
__global__ void k_agg(const int* __restrict__ row_ptr, const int* __restrict__ csr,
                      const __half2* __restrict__ h, const float* __restrict__ asrc,
                      const float* __restrict__ adst,
                      const float* __restrict__ bias, const float* __restrict__ gam,
                      const float* __restrict__ bet, const float* __restrict__ rme,
                      const float* __restrict__ rva,
                      OutT* __restrict__ out, int N) {
    constexpr int H2  = F / 2;
    constexpr int VPL = (H2 + 31) / 32;
    int warp = (blockIdx.x * blockDim.x + threadIdx.x) >> 5;
    int lane = threadIdx.x & 31;
    if (warp >= N) return;
    int n = warp;
    int beg = row_ptr[n], end = row_ptr[n + 1];
    float adn = adst[n];

    float2 acc[VPL];
#pragma unroll
    for (int v = 0; v < VPL; v++) acc[v] = make_float2(0.f, 0.f);
    float dsum = 0.f;

    for (int base = beg; base < end; base += 32) {
        int cnt = min(32, end - base);
        float w = 0.f; int s = 0;
        if (lane < cnt) {
            s = csr[base + lane];
            w = __expf(leaky(asrc[s] + adn));
        }
        dsum += w;
        for (int j = 0; j < cnt; j++) {
            float wj = __shfl_sync(0xffffffffu, w, j);
            int   sj = __shfl_sync(0xffffffffu, s, j);
            const __half2* hp = h + (size_t)sj * H2;
#pragma unroll
            for (int v = 0; v < VPL; v++) {
                int f2 = v * 32 + lane;
                if ((H2 % 32 == 0) || f2 < H2) {
                    float2 hv = __half22float2(__ldg(hp + f2));
                    acc[v].x = fmaf(wj, hv.x, acc[v].x);
                    acc[v].y = fmaf(wj, hv.y, acc[v].y);
                }
            }
        }
    }
#pragma unroll
    for (int o = 16; o; o >>= 1) dsum += __shfl_xor_sync(0xffffffffu, dsum, o);
    float inv = 1.0f / dsum;

#pragma unroll
    for (int v = 0; v < VPL; v++) {
        int f2 = v * 32 + lane;
        if ((H2 % 32) && f2 >= H2) continue;
        int f = f2 * 2;
        float v0 = acc[v].x * inv + bias[f];
        float v1 = acc[v].y * inv + bias[f + 1];
        if (MODE == 0) {
            v0 = tanhf((v0 - rme[f])     * rsqrtf(rva[f]     + BN_EPS) * gam[f]     + bet[f]);
            v1 = tanhf((v1 - rme[f + 1]) * rsqrtf(rva[f + 1] + BN_EPS) * gam[f + 1] + bet[f + 1]);
            *(__half2*)((__half*)out + (size_t)n * F + f) = __floats2half2_rn(v0, v1);
        } else {
            ((float*)out)[(size_t)n * F + f]     = v0;
            ((float*)out)[(size_t)n * F + f + 1] = v1;
        }
    }
}

// ---------------- launch ----------------
extern "C" void kernel_launch(void* const* d_in, const int* in_sizes, int n_in,
                              void* d_out, int out_size) {
    const float* x  = (const float*)d_in[0];
    const int*   ei = (const int*)d_in[1];   // int32 (JAX x64 disabled)
    const float* w1  = (const float*)d_in[2];
    const float* as1 = (const float*)d_in[3];
    const float* ad1 = (const float*)d_in[4];
    const float* b1  = (const float*)d_in[5];
    const float* g1  = (const float*)d_in[6];
    const float* be1 = (const float*)d_in[7];
    const float* rm1 = (const float*)d_in[8];
    const float* rv1 = (const float*)d_in[9];
    const float* w2  = (const float*)d_in[10];
    const float* as2 = (const float*)d_in[11];
    const float* ad2 = (const float*)d_in[12];
    const float* b2  = (const float*)d_in[13];
    const float* g2  = (const float*)d_in[14];
    const float* be2 = (const float*)d_in[15];
    const float* rm2 = (const float*)d_in[16];
    const float* rv2 = (const float*)d_in[17];
    const float* w3  = (const float*)d_in[18];
    const float* as3 = (const float*)d_in[19];
    const float* ad3 = (const float*)d_in[20];
    const float* b3  = (const float*)d_in[21];
    float* out = (float*)d_out;

    int N = in_sizes[0] / 128;
    int E = in_sizes[1] / 2;

    __half *h16, *xh, *wh;
    float *as_, *ad_;
    int *rowptr, *counts, *scan, *cursor, *csr, *bsums;
    cudaGetSymbolAddress((void**)&h16,    g_h16);
    cudaGetSymbolAddress((void**)&xh,     g_xh);
    cudaGetSymbolAddress((void**)&wh,     g_wh);
    cudaGetSymbolAddress((void**)&as_,    g_as);
    cudaGetSymbolAddress((void**)&ad_,    g_ad);
    cudaGetSymbolAddress((void**)&rowptr, g_rowptr);
    cudaGetSymbolAddress((void**)&counts, g_counts);
    cudaGetSymbolAddress((void**)&scan,   g_scan);
    cudaGetSymbolAddress((void**)&cursor, g_cursor);
    cudaGetSymbolAddress((void**)&csr,    g_csr);
    cudaGetSymbolAddress((void**)&bsums,  g_bsums);

    __half* w1h = wh;            // 128*128 = 16384
    __half* w2h = wh + 16384;    // 128*256 = 32768
    __half* w3h = wh + 49152;    // 256*40  = 10240

    int NB = (N + 255) / 256;
    int rowBlocks = (N + BM - 1) / BM;
    int aggBlocks = (N + 7) / 8;   // 8 warps/block

    // Launch order keeps gemm1 at position 4 for ncu sampling.
    k_initcount<<<NB, 256>>>(counts, as_, ad_, N);                              // 1
    k_f2h<<<(N * 128 / 2 + 255) / 256, 256>>>(x, xh, N * 128 / 2);              // 2
    k_f2h<<<(16384 / 2 + 255) / 256, 256>>>(w1, w1h, 16384 / 2);                // 3
    k_gemm_f16<<<dim3(2, rowBlocks), 256, GEMM_SMEM_BYTES>>>                    // 4 (PROFILED)
        (xh, w1h, h16, as1, ad1, as_, ad_, N, 128, 128);
    k_f2h<<<(32768 / 2 + 255) / 256, 256>>>(w2, w2h, 32768 / 2);                // 5
    k_f2h<<<(10240 / 2 + 255) / 256, 256>>>(w3, w3h, 10240 / 2);                // 6
    k_count<<<(E + 255) / 256, 256>>>(ei, counts, E);                           // 7
    k_scan1<<<NB, 256>>>(counts, scan, bsums, N);                               // 8
    k_scan2<<<1, 512>>>(bsums, NB);                                             // 9
    k_scan3<<<NB, 256>>>(counts, scan, bsums, rowptr, cursor, csr, N);          // 10
    k_fill<<<(E + 255) / 256, 256>>>(ei, cursor, csr, E);                       // 11

    // ---- layer 1 agg -> xh (fp16) ----
    k_agg<128, 0, __half><<<aggBlocks, 256>>>(rowptr, csr, (const __half2*)h16, as_, ad_,
                                              b1, g1, be1, rm1, rv1, xh, N);

    // ---- layer 2: xh[N,128] @ w2h[128,256] ----
    cudaMemsetAsync(as_, 0, N * sizeof(float));
    cudaMemsetAsync(ad_, 0, N * sizeof(float));
    k_gemm_f16<<<dim3(4, rowBlocks), 256, GEMM_SMEM_BYTES>>>
        (xh, w2h, h16, as2, ad2, as_, ad_, N, 128, 256);
    k_agg<256, 0, __half><<<aggBlocks, 256>>>(rowptr, csr, (const __half2*)h16, as_, ad_,
                                              b2, g2, be2, rm2, rv2, xh, N);

    // ---- layer 3: xh[N,256] @ w3h[256,40] ----
    cudaMemsetAsync(as_, 0, N * sizeof(float));
    cudaMemsetAsync(ad_, 0, N * sizeof(float));
    k_gemm_f16<<<dim3(1, rowBlocks), 256, GEMM_SMEM_BYTES>>>
        (xh, w3h, h16, as3, ad3, as_, ad_, N, 256, 40);
    k_agg<40, 1, float><<<aggBlocks, 256>>>(rowptr, csr, (const __half2*)h16, as_, ad_,
                                            b3, b3, b3, b3, b3, out, N);
}

// round 13
// speedup vs baseline: 2.6321x; 1.1161x over previous
#include <cuda_runtime.h>
#include <cuda_fp16.h>
#include <mma.h>
#include <math.h>
#include <cstdint>

using namespace nvcuda;

#define NMAX 100000
#define EMAX 1600000
#define CSRMAX (EMAX + NMAX)
#define BN_EPS 1e-5f
#define NEG_SLOPE 0.2f

// fp16 GEMM tiling: BM=128, BN=64, BK=32, 256 threads (8 warps @ 32x32)
#define BM 128
#define BNT 64
#define BKT 32
#define A_STRIDE 40
#define B_STRIDE 72
#define A_STAGE (BM * A_STRIDE)
#define B_STAGE (BKT * B_STRIDE)
#define GEMM_SMEM_BYTES (BM * BNT * 4)   // 32KB fp32 Csh; pipeline (29.7KB) aliases it

// ---------------- scratch (device globals; no allocs allowed) ----------------
__device__ __half g_h16[(size_t)NMAX * 256];  // buffer A (h1, z2, h3)
__device__ __half g_xh[(size_t)NMAX * 256];   // buffer B (x, x2, x3)
__device__ __half g_wh[65536];                // fp16 weights: w1@0, w2@16384, w3@49152
__device__ float  g_as[NMAX];
__device__ float  g_ad[NMAX];
__device__ float  g_as2[NMAX];
__device__ float  g_ad2[NMAX];
__device__ float  g_va[768];                  // va2s[0:128] va2d[128:256] va3s[256:512] va3d[512:768]
__device__ int    g_rowptr[NMAX + 1];
__device__ int    g_counts[NMAX];
__device__ int    g_scan[NMAX];
__device__ int    g_cursor[NMAX];
__device__ int    g_csr[CSRMAX];
__device__ int    g_bsums[512];

// ---------------- cp.async helpers ----------------
__device__ __forceinline__ void cp_async16(void* dst, const void* src, bool pred) {
    unsigned int d = (unsigned int)__cvta_generic_to_shared(dst);
    int sz = pred ? 16 : 0;
    asm volatile("cp.async.cg.shared.global [%0],[%1],16,%2;\n" :: "r"(d), "l"(src), "r"(sz));
}
__device__ __forceinline__ void cp_commit() { asm volatile("cp.async.commit_group;\n"); }
__device__ __forceinline__ void cp_wait1() { asm volatile("cp.async.wait_group 1;\n"); }
__device__ __forceinline__ void cp_wait0() { asm volatile("cp.async.wait_group 0;\n"); }

// ---------------- small utility kernels ----------------
__global__ void k_zero2(float* a, float* b, int N) {
    int i = blockIdx.x * blockDim.x + threadIdx.x;
    if (i < N) { a[i] = 0.f; b[i] = 0.f; }
}
__global__ void k_f2h(const float* __restrict__ in, __half* __restrict__ out, int n2) {
    int i = blockIdx.x * blockDim.x + threadIdx.x;
    if (i < n2) {
        float2 v = ((const float2*)in)[i];
        ((__half2*)out)[i] = __floats2half2_rn(v.x, v.y);
    }
}
// va_s[k] = sum_n W[k,n]*as[n]; va_d likewise. One warp per k.
__global__ void k_wav(const float* __restrict__ W, const float* __restrict__ avs,
                      const float* __restrict__ avd, float* vs, float* vd, int K, int Nn) {
    int k = (blockIdx.x * blockDim.x + threadIdx.x) >> 5;
    int lane = threadIdx.x & 31;
    if (k >= K) return;
    float s = 0.f, d = 0.f;
    for (int n = lane; n < Nn; n += 32) {
        float w = W[(size_t)k * Nn + n];
        s = fmaf(w, avs[n], s);
        d = fmaf(w, avd[n], d);
    }
#pragma unroll
    for (int o = 16; o; o >>= 1) {
        s += __shfl_xor_sync(0xffffffffu, s, o);
        d += __shfl_xor_sync(0xffffffffu, d, o);
    }
    if (lane == 0) { vs[k] = s; vd[k] = d; }
}

// ---------------- CSR build ----------------
__global__ void k_initcount(int* counts, int N) {
    int i = blockIdx.x * blockDim.x + threadIdx.x;
    if (i < N) counts[i] = 1;  // self loop pre-counted
}
__global__ void k_count(const int* __restrict__ ei, int* counts, int E) {
    int e = blockIdx.x * blockDim.x + threadIdx.x;
    if (e < E) atomicAdd(&counts[ei[E + e]], 1);
}
__global__ void k_scan1(const int* __restrict__ counts, int* scanned, int* bsums, int N) {
    __shared__ int sh[256];
    int tid = threadIdx.x;
    int i = blockIdx.x * 256 + tid;
    int v = (i < N) ? counts[i] : 0;
    sh[tid] = v; __syncthreads();
    for (int o = 1; o < 256; o <<= 1) {
        int t = (tid >= o) ? sh[tid - o] : 0;
        __syncthreads();
        sh[tid] += t;
        __syncthreads();
    }
    if (i < N) scanned[i] = sh[tid];
    if (tid == 255) bsums[blockIdx.x] = sh[255];
}
__global__ void k_scan2(int* bsums, int NB) {
    __shared__ int sh[512];
    int tid = threadIdx.x;
    int v = (tid < NB) ? bsums[tid] : 0;
    sh[tid] = v; __syncthreads();
    for (int o = 1; o < 512; o <<= 1) {
        int t = (tid >= o) ? sh[tid - o] : 0;
        __syncthreads();
        sh[tid] += t;
        __syncthreads();
    }
    if (tid < NB) bsums[tid] = sh[tid];
}
__global__ void k_scan3(const int* __restrict__ counts, const int* __restrict__ scanned,
                        const int* __restrict__ bsums, int* row_ptr, int* cursor,
                        int* csr, int N) {
    int i = blockIdx.x * 256 + threadIdx.x;
    if (i >= N) return;
    int off = blockIdx.x ? bsums[blockIdx.x - 1] : 0;
    int incl = off + scanned[i];
    int rp = incl - counts[i];
    row_ptr[i] = rp;
    csr[rp] = i;
    cursor[i] = rp + 1;
    if (i == N - 1) row_ptr[N] = incl;
}
__global__ void k_fill(const int* __restrict__ ei, int* cursor, int* csr, int E) {
    int e = blockIdx.x * blockDim.x + threadIdx.x;
    if (e < E) {
        int d = ei[E + e];
        int s = ei[e];
        int pos = atomicAdd(&cursor[d], 1);
        csr[pos] = s;
    }
}

// ---------------- fp16 tensor-core GEMM, cp.async double-buffered ----------------
// EPI 0: H = fp16(C); as_o[m] += C·avs, ad_o[m] += C·avd (atomic)   [layer 1]
// EPI 1: v = tanh(BN(C + bias)); H = fp16(v); as_o[m] += v·avs ...  [layer 2]
// EPI 2: H = fp16(C); no dots                                        [layer 3]
template <int EPI>
__global__ __launch_bounds__(256, 2) void k_gemm_f16(
        const __half* __restrict__ A, const __half* __restrict__ B,
        __half* __restrict__ H,
        const float* __restrict__ avs, const float* __restrict__ avd,
        float* __restrict__ as_o, float* __restrict__ ad_o,
        const float* __restrict__ bias, const float* __restrict__ gam,
        const float* __restrict__ bet, const float* __restrict__ rme,
        const float* __restrict__ rva,
        int M, int K, int Nn) {
    extern __shared__ __half smemh[];
    __half* Asm = smemh;
    __half* Bsm = smemh + 2 * A_STAGE;
    float*  Csh = (float*)smemh;

    int tid  = threadIdx.x;
    int warp = tid >> 5;
    int wm   = warp >> 1;
    int wn   = warp & 1;
    int row0 = blockIdx.y * BM;
    int col0 = blockIdx.x * BNT;
    int ntiles = K / BKT;

    wmma::fragment<wmma::accumulator, 16, 16, 16, float> c[2][2];
#pragma unroll
    for (int i = 0; i < 2; i++)
#pragma unroll
        for (int j = 0; j < 2; j++) wmma::fill_fragment(c[i][j], 0.f);

    int ar = tid >> 1;
    int ac = (tid & 1) * 16;
    int br = tid >> 3;
    int bc = (tid & 7) * 8;

    auto issue = [&](int t, int s) {
        int k0 = t * BKT;
        const __half* asrc = A + (size_t)(row0 + ar) * K + k0 + ac;
        __half* adst = Asm + s * A_STAGE + ar * A_STRIDE + ac;
        bool am = (row0 + ar) < M;
        cp_async16(adst,     asrc,     am);
        cp_async16(adst + 8, asrc + 8, am);
        int nn = col0 + bc;
        const __half* bsrc = B + (size_t)(k0 + br) * Nn + nn;
        __half* bdst = Bsm + s * B_STAGE + br * B_STRIDE + bc;
        cp_async16(bdst, bsrc, nn < Nn);
    };

    issue(0, 0); cp_commit();

    for (int t = 0; t < ntiles; t++) {
        if (t + 1 < ntiles) { issue(t + 1, (t + 1) & 1); cp_commit(); cp_wait1(); }
        else                { cp_wait0(); }
        __syncthreads();
        const __half* As = Asm + (t & 1) * A_STAGE;
        const __half* Bs = Bsm + (t & 1) * B_STAGE;
#pragma unroll
        for (int kk = 0; kk < BKT; kk += 16) {
            wmma::fragment<wmma::matrix_a, 16, 16, 16, __half, wmma::row_major> a[2];
            wmma::fragment<wmma::matrix_b, 16, 16, 16, __half, wmma::row_major> b[2];
#pragma unroll
            for (int i = 0; i < 2; i++)
                wmma::load_matrix_sync(a[i], As + (wm * 32 + i * 16) * A_STRIDE + kk, A_STRIDE);
#pragma unroll
            for (int j = 0; j < 2; j++)
                wmma::load_matrix_sync(b[j], Bs + kk * B_STRIDE + wn * 32 + j * 16, B_STRIDE);
#pragma unroll
            for (int i = 0; i < 2; i++)
#pragma unroll
                for (int j = 0; j < 2; j++)
                    wmma::mma_sync(c[i][j], a[i], b[j], c[i][j]);
        }
        __syncthreads();
    }

#pragma unroll
    for (int i = 0; i < 2; i++)
#pragma unroll
        for (int j = 0; j < 2; j++)
            wmma::store_matrix_sync(Csh + (wm * 32 + i * 16) * BNT + wn * 32 + j * 16,
                                    c[i][j], BNT, wmma::mem_row_major);
    __syncthreads();

    int r  = tid >> 1;
    int n0 = (tid & 1) * 32;
    int m  = row0 + r;
    if (m >= M) return;
    float pas = 0.f, pad = 0.f;
    __half* hp = H + (size_t)m * Nn;
#pragma unroll 16
    for (int cc = 0; cc < 32; cc += 2) {
        int n = n0 + cc;
        int g = col0 + n;
        if (g >= Nn) break;   // Nn even; pairs stay valid together
        float v0 = Csh[r * BNT + n];
        float v1 = Csh[r * BNT + n + 1];
        if (EPI == 1) {
            v0 = tanhf((v0 + bias[g]     - rme[g])     * rsqrtf(rva[g]     + BN_EPS) * gam[g]     + bet[g]);
            v1 = tanhf((v1 + bias[g + 1] - rme[g + 1]) * rsqrtf(rva[g + 1] + BN_EPS) * gam[g + 1] + bet[g + 1]);
        }
        if (EPI != 2) {
            pas = fmaf(v0, avs[g], fmaf(v1, avs[g + 1], pas));
            pad = fmaf(v0, avd[g], fmaf(v1, avd[g + 1], pad));
        }
        *(__half2*)(hp + g) = __floats2half2_rn(v0, v1);
    }
    if (EPI != 2) {
        atomicAdd(&as_o[m], pas);
        atomicAdd(&ad_o[m], pad);
    }
}

__device__ __forceinline__ float leaky(float v) {
    return v > 0.f ? v : NEG_SLOPE * v;
}

// ---------------- warp-per-node softmax aggregation ----------------
// MODE 0: out fp16 = tanh(BN(acc*inv + bias)); also dots with vas/vad -> as_out/ad_out (plain)
// MODE 1: out fp32 = acc*inv + bias
// MODE 2: out fp16 = acc*inv (raw, pre-GEMM)
template <int F, int MODE, typename OutT>
__global__ void k_agg(const int* __restrict__ row_ptr, const int* __restrict__ csr,
                      const __half2* __restrict__ h, const float* __restrict__ asrc,
                      const float* __restrict__ adst,
                      const float* __restrict__ bias, const float* __restrict__ gam,
                      const float* __restrict__ bet, const float* __restrict__ rme,
                      const float* __restrict__ rva,
                      const float* __restrict__ vas, const float* __restrict__ vad,
                      float* __restrict__ as_out, float* __restrict__ ad_out,
                      OutT* __restrict__ out, int N) {
    constexpr int H2  = F / 2;
    constexpr int VPL = (H2 + 31) / 32;
    int warp = (blockIdx.x * blockDim.x + threadIdx.x) >> 5;
    int lane = threadIdx.x & 31;
    if (warp >= N) return;
    int n = warp;
    int beg = row_ptr[n], end = row_ptr[n + 1];
    float adn = adst[n];

    float2 acc[VPL];
#pragma unroll
    for (int v = 0; v < VPL; v++) acc[v] = make_float2(0.f, 0.f);
    float dsum = 0.f;

    for (int base = beg; base < end; base += 32) {
        int cnt = min(32, end - base);
        float w = 0.f; int s = 0;
        if (lane < cnt) {
            s = csr[base + lane];
            w = __expf(leaky(asrc[s] + adn));
        }
        dsum += w;
        for (int j = 0; j < cnt; j++) {
            float wj = __shfl_sync(0xffffffffu, w, j);
            int   sj = __shfl_sync(0xffffffffu, s, j);
            const __half2* hp = h + (size_t)sj * H2;
#pragma unroll
            for (int v = 0; v < VPL; v++) {
                int f2 = v * 32 + lane;
                if ((H2 % 32 == 0) || f2 < H2) {
                    float2 hv = __half22float2(__ldg(hp + f2));
                    acc[v].x = fmaf(wj, hv.x, acc[v].x);
                    acc[v].y = fmaf(wj, hv.y, acc[v].y);
                }
            }
        }
    }
#pragma unroll
    for (int o = 16; o; o >>= 1) dsum += __shfl_xor_sync(0xffffffffu, dsum, o);
    float inv = 1.0f / dsum;

    float pa = 0.f, pd = 0.f;
#pragma unroll
    for (int v = 0; v < VPL; v++) {
        int f2 = v * 32 + lane;
        if ((H2 % 32) && f2 >= H2) continue;
        int f = f2 * 2;
        float v0 = acc[v].x * inv;
        float v1 = acc[v].y * inv;
        if (MODE == 0) {
            v0 = tanhf((v0 + bias[f]     - rme[f])     * rsqrtf(rva[f]     + BN_EPS) * gam[f]     + bet[f]);
            v1 = tanhf((v1 + bias[f + 1] - rme[f + 1]) * rsqrtf(rva[f + 1] + BN_EPS) * gam[f + 1] + bet[f + 1]);
            pa = fmaf(v0, vas[f], fmaf(v1, vas[f + 1], pa));
            pd = fmaf(v0, vad[f], fmaf(v1, vad[f + 1], pd));
            *(__half2*)((__half*)out + (size_t)n * F + f) = __floats2half2_rn(v0, v1);
        } else if (MODE == 2) {
            *(__half2*)((__half*)out + (size_t)n * F + f) = __floats2half2_rn(v0, v1);
        } else {
            ((float*)out)[(size_t)n * F + f]     = v0 + bias[f];
            ((float*)out)[(size_t)n * F + f + 1] = v1 + bias[f + 1];
        }
    }
    if (MODE == 0) {
#pragma unroll
        for (int o = 16; o; o >>= 1) {
            pa += __shfl_xor_sync(0xffffffffu, pa, o);
            pd += __shfl_xor_sync(0xffffffffu, pd, o);
        }
        if (lane == 0) { as_out[n] = pa; ad_out[n] = pd; }
    }
}

// ---------------- launch ----------------
extern "C" void kernel_launch(void* const* d_in, const int* in_sizes, int n_in,
                              void* d_out, int out_size) {
    const float* x  = (const float*)d_in[0];
    const int*   ei = (const int*)d_in[1];   // int32 (JAX x64 disabled)
    const float* w1  = (const float*)d_in[2];
    const float* as1 = (const float*)d_in[3];
    const float* ad1 = (const float*)d_in[4];
    const float* b1  = (const float*)d_in[5];
    const float* g1  = (const float*)d_in[6];
    const float* be1 = (const float*)d_in[7];
    const float* rm1 = (const float*)d_in[8];
    const float* rv1 = (const float*)d_in[9];
    const float* w2  = (const float*)d_in[10];
    const float* as2 = (const float*)d_in[11];
    const float* ad2 = (const float*)d_in[12];
    const float* b2  = (const float*)d_in[13];
    const float* g2  = (const float*)d_in[14];
    const float* be2 = (const float*)d_in[15];
    const float* rm2 = (const float*)d_in[16];
    const float* rv2 = (const float*)d_in[17];
    const float* w3  = (const float*)d_in[18];
    const float* as3 = (const float*)d_in[19];
    const float* ad3 = (const float*)d_in[20];
    const float* b3  = (const float*)d_in[21];
    float* out = (float*)d_out;

    int N = in_sizes[0] / 128;
    int E = in_sizes[1] / 2;

    __half *h16, *xh, *wh;
    float *as_, *ad_, *as2b, *ad2b, *va;
    int *rowptr, *counts, *scan, *cursor, *csr, *bsums;
    cudaGetSymbolAddress((void**)&h16,    g_h16);
    cudaGetSymbolAddress((void**)&xh,     g_xh);
    cudaGetSymbolAddress((void**)&wh,     g_wh);
    cudaGetSymbolAddress((void**)&as_,    g_as);
    cudaGetSymbolAddress((void**)&ad_,    g_ad);
    cudaGetSymbolAddress((void**)&as2b,   g_as2);
    cudaGetSymbolAddress((void**)&ad2b,   g_ad2);
    cudaGetSymbolAddress((void**)&va,     g_va);
    cudaGetSymbolAddress((void**)&rowptr, g_rowptr);
    cudaGetSymbolAddress((void**)&counts, g_counts);
    cudaGetSymbolAddress((void**)&scan,   g_scan);
    cudaGetSymbolAddress((void**)&cursor, g_cursor);
    cudaGetSymbolAddress((void**)&csr,    g_csr);
    cudaGetSymbolAddress((void**)&bsums,  g_bsums);

    __half* w1h = wh;
    __half* w2h = wh + 16384;
    __half* w3h = wh + 49152;
    float* va2s = va;        float* va2d = va + 128;
    float* va3s = va + 256;  float* va3d = va + 512;

    int NB = (N + 255) / 256;
    int gemmSmem = GEMM_SMEM_BYTES;
    int rowBlocks = (N + BM - 1) / BM;
    int aggBlocks = (N + 7) / 8;

    // ---- layer 1 GEMM at launch position 4 (ncu sampling) ----
    k_zero2<<<NB, 256>>>(as_, ad_, N);                                          // 1
    k_f2h<<<(N * 128 / 2 + 255) / 256, 256>>>(x, xh, N * 128 / 2);              // 2
    k_f2h<<<(16384 / 2 + 255) / 256, 256>>>(w1, w1h, 16384 / 2);                // 3
    k_gemm_f16<0><<<dim3(2, rowBlocks), 256, gemmSmem>>>                        // 4 (PROFILED)
        (xh, w1h, h16, as1, ad1, as_, ad_,
         b1, b1, b1, b1, b1, N, 128, 128);
    k_f2h<<<(32768 / 2 + 255) / 256, 256>>>(w2, w2h, 32768 / 2);                // 5
    k_f2h<<<(10240 / 2 + 255) / 256, 256>>>(w3, w3h, 10240 / 2);                // 6
    k_wav<<<(128 * 32 + 255) / 256, 256>>>(w2, as2, ad2, va2s, va2d, 128, 256); // 7
    k_wav<<<(256 * 32 + 255) / 256, 256>>>(w3, as3, ad3, va3s, va3d, 256, 40);  // 8
    k_initcount<<<NB, 256>>>(counts, N);                                        // 9
    k_count<<<(E + 255) / 256, 256>>>(ei, counts, E);                           // 10
    k_scan1<<<NB, 256>>>(counts, scan, bsums, N);                               // 11
    k_scan2<<<1, 512>>>(bsums, NB);                                             // 12
    k_scan3<<<NB, 256>>>(counts, scan, bsums, rowptr, cursor, csr, N);          // 13
    k_fill<<<(E + 255) / 256, 256>>>(ei, cursor, csr, E);                       // 14

    // ---- agg1: gather h1 -> x2 (fp16, in xh) + as2/ad2 dots ----
    k_agg<128, 0, __half><<<aggBlocks, 256>>>(rowptr, csr, (const __half2*)h16, as_, ad_,
                                              b1, g1, be1, rm1, rv1,
                                              va2s, va2d, as2b, ad2b, xh, N);

    // ---- agg2 in x-space: gather x2 -> z2 (fp16, in h16) ----
    k_agg<128, 2, __half><<<aggBlocks, 256>>>(rowptr, csr, (const __half2*)xh, as2b, ad2b,
                                              b2, b2, b2, b2, b2,
                                              va2s, va2d, as2b, ad2b, h16, N);

    // ---- gemm2: z2 @ W2, epilogue bias+BN+tanh -> x3 (xh) + as3/ad3 dots ----
    k_zero2<<<NB, 256>>>(as_, ad_, N);
    k_gemm_f16<1><<<dim3(4, rowBlocks), 256, gemmSmem>>>
        (h16, w2h, xh, va3s, va3d, as_, ad_,
         b2, g2, be2, rm2, rv2, N, 128, 256);

    // ---- gemm3: x3 @ W3 -> h3 (h16, [N,40]) ----
    k_gemm_f16<2><<<dim3(1, rowBlocks), 256, gemmSmem>>>
        (xh, w3h, h16, va3s, va3d, as_, ad_,
         b3, b3, b3, b3, b3, N, 256, 40);

    // ---- agg3: gather h3 + b3 -> out (fp32) ----
    k_agg<40, 1, float><<<aggBlocks, 256>>>(rowptr, csr, (const __half2*)h16, as_, ad_,
                                            b3, b3, b3, b3, b3,
                                            va3s, va3d, as2b, ad2b, out, N);
}